// round 10
// baseline (speedup 1.0000x reference)
#include <cuda_runtime.h>
#include <cuda_bf16.h>
#include <cuda_fp16.h>
#include <math.h>
#include <stdint.h>

#define NROI 1024
#define NCLS 21
#define APP  1024
#define DF   128
#define NH   16
#define DK   64

typedef unsigned long long ull;
typedef unsigned int u32;

// ---------------- f32x2 packed-math helpers (sm_103a) -------------------------
__device__ __forceinline__ ull pk2(float lo, float hi) {
    ull r; asm("mov.b64 %0,{%1,%2};" : "=l"(r) : "f"(lo), "f"(hi)); return r;
}
__device__ __forceinline__ float2 upk(ull v) {
    float2 f; asm("mov.b64 {%0,%1},%2;" : "=f"(f.x), "=f"(f.y) : "l"(v)); return f;
}
__device__ __forceinline__ void fma2(ull &c, ull a, ull b) {
    asm("fma.rn.f32x2 %0,%1,%2,%0;" : "+l"(c) : "l"(a), "l"(b));
}

// ---------------- HMMA m16n8k16 bf16 ------------------------------------------
__device__ __forceinline__ void mma_bf16(float* c, const u32* a, const u32* b) {
    asm volatile("mma.sync.aligned.m16n8k16.row.col.f32.bf16.bf16.f32 "
        "{%0,%1,%2,%3},{%4,%5,%6,%7},{%8,%9},{%0,%1,%2,%3};"
        : "+f"(c[0]), "+f"(c[1]), "+f"(c[2]), "+f"(c[3])
        : "r"(a[0]), "r"(a[1]), "r"(a[2]), "r"(a[3]), "r"(b[0]), "r"(b[1]));
}

// ---------------- scratch (device globals; no allocation allowed) -------------
__device__ __half g_Sh[NH * NROI * NROI];     // 32 MB scores fp16 [h][m][n]
__device__ __align__(16) __nv_bfloat16 g_Kh[NH*NROI*DK], g_Kl[NH*NROI*DK];
__device__ __align__(16) __nv_bfloat16 g_Qh[NH*NROI*DK], g_Ql[NH*NROI*DK];
__device__ __align__(16) float g_RE[NROI * APP];   // rank embedding matrix
__device__ __align__(16) float g_emb[NROI * DF];
__device__ float g_vl[NH * NROI];
__device__ float g_wvl[NH * DF];
__device__ float g_bvl[NH];
__device__ float g_prob[NROI], g_sprob[NROI], g_sflw[NROI];
__device__ float g_bbox[NROI * 4], g_sbbox[NROI * 4];
__device__ __align__(16) float4 g_geoA[NROI];   // cx, cy, log w, log h
__device__ __align__(8)  float2 g_geoB[NROI];   // 1/w, 1/h
__device__ int   g_label[NROI], g_slabel[NROI], g_order[NROI];

// ---------------- K1: per-ROI decode (blocks 0-3) + wvl (blocks 4-19) ---------
__global__ __launch_bounds__(256) void k_front(const float* __restrict__ roi,
                                               const float* __restrict__ cls_loc,
                                               const float* __restrict__ score,
                                               const int*   __restrict__ size,
                                               const float* __restrict__ wv_w,
                                               const float* __restrict__ wv_b,
                                               const float* __restrict__ lw) {
    __shared__ float lwh[DK];
    int b = blockIdx.x, t = threadIdx.x;
    if (b < 4) {
        int i = b * 256 + t;
        const float* s = score + i * NCLS;
        float mx = -1e30f; int am = 0;
        for (int c = 0; c < NCLS; c++) { float v = s[c]; if (v > mx) { mx = v; am = c; } }
        float sum = 0.f;
        for (int c = 0; c < NCLS; c++) sum += expf(s[c] - mx);
        g_prob[i] = 1.0f / sum;
        g_label[i] = am;
        float y0 = roi[i*4+0], x0 = roi[i*4+1], y1 = roi[i*4+2], x1 = roi[i*4+3];
        float h = y1 - y0, w = x1 - x0;
        float cy = y0 + 0.5f * h, cx = x0 + 0.5f * w;
        const float* l = cls_loc + i * (NCLS*4) + am * 4;
        float dy = l[0]*0.1f, dx = l[1]*0.1f, dh = l[2]*0.2f, dw = l[3]*0.2f;
        float ncy = dy*h + cy, ncx = dx*w + cx;
        float nh = expf(dh)*h, nw = expf(dw)*w;
        float b0 = ncy - 0.5f*nh, b1 = ncx - 0.5f*nw, b2 = ncy + 0.5f*nh, b3 = ncx + 0.5f*nw;
        // reference clamp quirk: even class -> all coords clamp to size[0], odd -> size[1]
        float lim = ((am & 1) == 0) ? (float)size[0] : (float)size[1];
        b0 = fminf(fmaxf(b0, 0.f), lim); b1 = fminf(fmaxf(b1, 0.f), lim);
        b2 = fminf(fmaxf(b2, 0.f), lim); b3 = fminf(fmaxf(b3, 0.f), lim);
        g_bbox[i*4+0]=b0; g_bbox[i*4+1]=b1; g_bbox[i*4+2]=b2; g_bbox[i*4+3]=b3;
        return;
    }
    int h = b - 4;
    if (t < DK) lwh[t] = lw[h * DK + t];
    __syncthreads();
    int d = t >> 1, half = t & 1;
    const float4* W  = (const float4*)(wv_w + (h * DF + d) * DK + half * 32);
    float a = 0.f;
    #pragma unroll
    for (int q = 0; q < 8; q++) {
        float4 w4 = W[q];
        const float* l4 = lwh + half * 32 + q * 4;
        a += w4.x*l4[0] + w4.y*l4[1] + w4.z*l4[2] + w4.w*l4[3];
    }
    a += __shfl_xor_sync(0xffffffffu, a, 1);
    if (!half) g_wvl[h * DF + d] = a;
    if (t < 32) {
        float pb = wv_b[h*DK + t] * lwh[t] + wv_b[h*DK + t + 32] * lwh[t + 32];
        #pragma unroll
        for (int o = 16; o; o >>= 1) pb += __shfl_xor_sync(0xffffffffu, pb, o);
        if (t == 0) g_bvl[h] = pb;
    }
}

// ---------------- K2: stable descending rank + scatter ------------------------
__global__ __launch_bounds__(256) void k_rank() {
    __shared__ float sp[NROI];
    int t = threadIdx.x;
    int i = blockIdx.x * 256 + t;
    for (int j = t; j < NROI; j += 256) sp[j] = g_prob[j];
    __syncthreads();
    float p = sp[i];
    int r = 0;
    for (int j = 0; j < NROI; j++) {
        float pj = sp[j];
        r += (pj > p) || (pj == p && j < i);
    }
    g_order[r]  = i;
    g_sprob[r]  = p;
    g_slabel[r] = g_label[i];
    float b0=g_bbox[i*4+0], b1=g_bbox[i*4+1], b2=g_bbox[i*4+2], b3=g_bbox[i*4+3];
    g_sbbox[r*4+0]=b0; g_sbbox[r*4+1]=b1; g_sbbox[r*4+2]=b2; g_sbbox[r*4+3]=b3;
    float cx = (b0+b2)*0.5f, cy = (b1+b3)*0.5f;
    float w  = (b2-b0)+1.0f, h  = (b3-b1)+1.0f;
    g_geoA[r] = make_float4(cx, cy, logf(w), logf(h));
    g_geoB[r] = make_float2(1.0f / w, 1.0f / h);
}

// ---------------- K2b: RE matrix generation + sflw dot (4 rows/block) ---------
__global__ __launch_bounds__(256) void k_pre(const float* __restrict__ app,
                                             const float* __restrict__ lw) {
    __shared__ int   soi[4];
    __shared__ float part[8];
    int r0 = blockIdx.x * 4, t = threadIdx.x;
    if (t < 4) soi[t] = g_order[r0 + t];
    __syncthreads();
    // sflw: 64 threads per row (2 warps)
    int row = t >> 6, j0 = t & 63;
    const float* ap = app + soi[row] * APP;
    float pl = 0.f;
    #pragma unroll
    for (int it = 0; it < 16; it++) pl += ap[j0 + it * 64] * lw[j0 + it * 64];
    int warp = t >> 5, lane = t & 31;
    #pragma unroll
    for (int o = 16; o; o >>= 1) pl += __shfl_xor_sync(0xffffffffu, pl, o);
    if (lane == 0) part[warp] = pl;
    // RE rows: each thread does 8 (row, freq) combos, precise sincosf
    const float LOGW = 6.90775527898f / 512.0f;
    #pragma unroll
    for (int it = 0; it < 8; it++) {
        int rr = it >> 1;
        int f = (it & 1) * 256 + t;
        float fr = expf(-(float)f * LOGW);
        float s, c;
        sincosf((float)(r0 + rr) * fr, &s, &c);
        g_RE[(r0 + rr) * APP + f]       = s;
        g_RE[(r0 + rr) * APP + 512 + f] = c;
    }
    __syncthreads();
    if (t < 4) g_sflw[r0 + t] = part[2 * t] + part[2 * t + 1];
}

// ---------------- K3: emb GEMM: [1024x128] = [app_s|RE][1024x2048] @ W --------
// tile: BM=16 rows, BN=64 cols, BK=32; grid (64, 2)
__global__ __launch_bounds__(256) void k_emb_g(const float* __restrict__ app,
                                               const float* __restrict__ feat_w,
                                               const float* __restrict__ rank_w,
                                               const float* __restrict__ feat_b,
                                               const float* __restrict__ rank_b) {
    __shared__ float a_s[32][17];
    __shared__ float w_s[32][68];
    __shared__ int   s_oi[16];
    int bm = blockIdx.x, bn = blockIdx.y;
    int row0 = bm * 16, col0 = bn * 64;
    int t = threadIdx.x;
    if (t < 16) s_oi[t] = g_order[row0 + t];
    __syncthreads();
    int arow = t >> 4, ak = (t & 15) * 2;      // A: 16 rows x (16 float2)
    int wk = t >> 3, wc = (t & 7) * 8;         // W: 32 k x (8 groups of 8)
    int ty = t >> 4, tx = t & 15;              // compute: 1 row, 4 cols
    ull acc0 = 0ull, acc1 = 0ull;
    for (int kc = 0; kc < 64; kc++) {
        int k0 = kc * 32;
        float2 av;
        if (k0 < 1024) av = *(const float2*)(app + s_oi[arow] * APP + k0 + ak);
        else           av = *(const float2*)(g_RE + (row0 + arow) * APP + (k0 - 1024) + ak);
        const float* Wsrc = (k0 < 1024) ? (feat_w + (k0 + wk) * DF + col0 + wc)
                                        : (rank_w + (k0 - 1024 + wk) * DF + col0 + wc);
        float4 w0 = *(const float4*)Wsrc;
        float4 w1 = *(const float4*)(Wsrc + 4);
        __syncthreads();
        a_s[ak][arow] = av.x; a_s[ak + 1][arow] = av.y;
        *(float4*)&w_s[wk][wc] = w0;
        *(float4*)&w_s[wk][wc + 4] = w1;
        __syncthreads();
        #pragma unroll
        for (int k = 0; k < 32; k++) {
            float a = a_s[k][ty];
            ull aa = pk2(a, a);
            ulonglong2 w2 = *(const ulonglong2*)&w_s[k][tx * 4];
            fma2(acc0, aa, w2.x);
            fma2(acc1, aa, w2.y);
        }
    }
    int col = col0 + tx * 4;
    float4 fb = *(const float4*)(feat_b + col);
    float4 rb = *(const float4*)(rank_b + col);
    float2 r0 = upk(acc0), r1 = upk(acc1);
    float4 o = make_float4(r0.x + fb.x + rb.x, r0.y + fb.y + rb.y,
                           r1.x + fb.z + rb.z, r1.y + fb.w + rb.w);
    *(float4*)(g_emb + (row0 + ty) * DF + col) = o;
}

// ---------------- K3b: vl[h][n] = emb[n].wvl[h] + bvl[h] (warp per n) ---------
__global__ __launch_bounds__(256) void k_vl() {
    int w = threadIdx.x >> 5, lane = threadIdx.x & 31;
    int n = blockIdx.x * 8 + w;
    float4 e4 = *(const float4*)(g_emb + n * DF + lane * 4);
    #pragma unroll
    for (int h = 0; h < NH; h++) {
        float4 wv = *(const float4*)(g_wvl + h * DF + lane * 4);
        float s = e4.x*wv.x + e4.y*wv.y + e4.z*wv.z + e4.w*wv.w;
        #pragma unroll
        for (int o = 16; o; o >>= 1) s += __shfl_xor_sync(0xffffffffu, s, o);
        if (lane == 0) g_vl[(h << 10) + n] = s + g_bvl[h];
    }
}

// ---------------- K4: k/q projection GEMM -> bf16 hi/lo -----------------------
// C[1024 rows n][2048 cols p], K=128; tile BM=64, BN=256, BK=32; grid (8 ct, 16 rt)
__global__ __launch_bounds__(256) void k_kqv_g(const float* __restrict__ wk_w,
                                               const float* __restrict__ wk_b,
                                               const float* __restrict__ wq_w,
                                               const float* __restrict__ wq_b) {
    __shared__ float a_s[32][68];
    __shared__ float w_s[32][260];
    int ct = blockIdx.x, rt = blockIdx.y;
    int row0 = rt * 64, t = threadIdx.x;
    bool isK = (ct < 4);
    int tx = t & 63, ty = t >> 6;              // 4 cols, 16 rows
    int lrow = t >> 2, lk8 = (t & 3) * 8;      // A loader: 64 rows x (4x float4 pairs)
    int wkk = t >> 3, wg = t & 7;              // W loader
    int wh = (isK ? ct * 4 : (ct - 4) * 4) + (wg >> 1);
    const float* Wbase = (isK ? wk_w : wq_w) + wh * DF * DK + (wg & 1) * 32;
    ull acc[8][4];
    #pragma unroll
    for (int rp = 0; rp < 8; rp++)
        #pragma unroll
        for (int c = 0; c < 4; c++) acc[rp][c] = 0ull;
    for (int kc = 0; kc < 4; kc++) {
        int k0 = kc * 32;
        float4 a0 = *(const float4*)(g_emb + (row0 + lrow) * DF + k0 + lk8);
        float4 a1 = *(const float4*)(g_emb + (row0 + lrow) * DF + k0 + lk8 + 4);
        float4 wv[8];
        #pragma unroll
        for (int j = 0; j < 8; j++)
            wv[j] = *(const float4*)(Wbase + (k0 + wkk) * DK + (j & 7) * 4);
        __syncthreads();
        a_s[lk8+0][lrow]=a0.x; a_s[lk8+1][lrow]=a0.y; a_s[lk8+2][lrow]=a0.z; a_s[lk8+3][lrow]=a0.w;
        a_s[lk8+4][lrow]=a1.x; a_s[lk8+5][lrow]=a1.y; a_s[lk8+6][lrow]=a1.z; a_s[lk8+7][lrow]=a1.w;
        #pragma unroll
        for (int j = 0; j < 8; j++)
            *(float4*)&w_s[wkk][wg * 32 + j * 4] = wv[j];
        __syncthreads();
        #pragma unroll
        for (int k = 0; k < 32; k++) {
            ulonglong2 ap[4];
            #pragma unroll
            for (int q = 0; q < 4; q++)
                ap[q] = *(const ulonglong2*)&a_s[k][ty * 16 + q * 4];
            float4 w4 = *(const float4*)&w_s[k][tx * 4];
            ull w0 = pk2(w4.x, w4.x), w1 = pk2(w4.y, w4.y);
            ull w2 = pk2(w4.z, w4.z), w3 = pk2(w4.w, w4.w);
            #pragma unroll
            for (int q = 0; q < 4; q++) {
                fma2(acc[q*2][0], ap[q].x, w0); fma2(acc[q*2][1], ap[q].x, w1);
                fma2(acc[q*2][2], ap[q].x, w2); fma2(acc[q*2][3], ap[q].x, w3);
                fma2(acc[q*2+1][0], ap[q].y, w0); fma2(acc[q*2+1][1], ap[q].y, w1);
                fma2(acc[q*2+1][2], ap[q].y, w2); fma2(acc[q*2+1][3], ap[q].y, w3);
            }
        }
    }
    // epilogue: +bias, split bf16 hi/lo, pack 4 cols -> u64 store
    int p0 = ct * 256 + tx * 4;
    int pp0 = isK ? p0 : p0 - 1024;
    int h = pp0 >> 6, kk = pp0 & 63;
    float4 bv = *(const float4*)((isK ? wk_b : wq_b) + pp0);
    __nv_bfloat16* Hh = isK ? g_Kh : g_Qh;
    __nv_bfloat16* Hl = isK ? g_Kl : g_Ql;
    #pragma unroll
    for (int rp = 0; rp < 8; rp++) {
        float2 c0 = upk(acc[rp][0]), c1 = upk(acc[rp][1]);
        float2 c2 = upk(acc[rp][2]), c3 = upk(acc[rp][3]);
        float vals[2][4] = {{c0.x + bv.x, c1.x + bv.y, c2.x + bv.z, c3.x + bv.w},
                            {c0.y + bv.x, c1.y + bv.y, c2.y + bv.z, c3.y + bv.w}};
        #pragma unroll
        for (int e = 0; e < 2; e++) {
            int n = row0 + ty * 16 + rp * 2 + e;
            u32 hi32[2], lo32[2];
            #pragma unroll
            for (int half2i = 0; half2i < 2; half2i++) {
                float va = vals[e][half2i*2], vb = vals[e][half2i*2+1];
                __nv_bfloat16 ha = __float2bfloat16(va);
                __nv_bfloat16 hb = __float2bfloat16(vb);
                float la = va - __bfloat162float(ha);
                float lb = vb - __bfloat162float(hb);
                hi32[half2i] = (u32)__bfloat16_as_ushort(ha) | ((u32)__bfloat16_as_ushort(hb) << 16);
                lo32[half2i] = (u32)__bfloat16_as_ushort(__float2bfloat16(la))
                             | ((u32)__bfloat16_as_ushort(__float2bfloat16(lb)) << 16);
            }
            ull hp = (ull)hi32[0] | ((ull)hi32[1] << 32);
            ull lp = (ull)lo32[0] | ((ull)lo32[1] << 32);
            *(ull*)(Hh + ((h << 10) + n) * DK + kk) = hp;
            *(ull*)(Hl + ((h << 10) + n) * DK + kk) = lp;
        }
    }
}

// ---------------- K5: HMMA bf16-split score GEMM -> fp16 S --------------------
#define LDP 33
__global__ __launch_bounds__(256) void k_score_mma() {
    extern __shared__ __align__(16) u32 sm[];
    u32* KHs = sm;
    u32* KLs = sm + 128 * LDP;
    u32* QHs = sm + 2 * 128 * LDP;
    u32* QLs = sm + 2 * 128 * LDP + 64 * LDP;
    int t = threadIdx.x;
    int nt = blockIdx.x, mt = blockIdx.y, h = blockIdx.z;
    const u32* gKH = (const u32*)g_Kh + ((h << 10) + mt * 128) * 32;
    const u32* gKL = (const u32*)g_Kl + ((h << 10) + mt * 128) * 32;
    const u32* gQH = (const u32*)g_Qh + ((h << 10) + nt * 64) * 32;
    const u32* gQL = (const u32*)g_Ql + ((h << 10) + nt * 64) * 32;
    #pragma unroll
    for (int it = 0; it < 16; it++) {
        int idx = t + it * 256;
        int row = idx >> 5, c = idx & 31;
        KHs[row * LDP + c] = gKH[idx];
        KLs[row * LDP + c] = gKL[idx];
    }
    #pragma unroll
    for (int it = 0; it < 8; it++) {
        int idx = t + it * 256;
        int row = idx >> 5, c = idx & 31;
        QHs[row * LDP + c] = gQH[idx];
        QLs[row * LDP + c] = gQL[idx];
    }
    __syncthreads();
    int wid = t >> 5, lane = t & 31;
    int m0 = (wid >> 1) * 32, n0 = (wid & 1) * 32;
    int r = lane >> 2, cp2 = (lane & 3) * 2;
    float acc[2][4][4];
    #pragma unroll
    for (int i = 0; i < 2; i++)
        #pragma unroll
        for (int j = 0; j < 4; j++)
            #pragma unroll
            for (int e = 0; e < 4; e++) acc[i][j][e] = 0.f;
    #pragma unroll
    for (int kc = 0; kc < 4; kc++) {
        int cb = kc * 8 + (cp2 >> 1);
        u32 ah[2][4], al[2][4];
        #pragma unroll
        for (int i = 0; i < 2; i++) {
            int ra = m0 + i * 16 + r;
            ah[i][0] = KHs[ra * LDP + cb];       al[i][0] = KLs[ra * LDP + cb];
            ah[i][1] = KHs[(ra+8) * LDP + cb];   al[i][1] = KLs[(ra+8) * LDP + cb];
            ah[i][2] = KHs[ra * LDP + cb + 4];   al[i][2] = KLs[ra * LDP + cb + 4];
            ah[i][3] = KHs[(ra+8) * LDP + cb+4]; al[i][3] = KLs[(ra+8) * LDP + cb+4];
        }
        u32 bh[4][2], bl[4][2];
        #pragma unroll
        for (int j = 0; j < 4; j++) {
            int rb = n0 + j * 8 + r;
            bh[j][0] = QHs[rb * LDP + cb];     bl[j][0] = QLs[rb * LDP + cb];
            bh[j][1] = QHs[rb * LDP + cb + 4]; bl[j][1] = QLs[rb * LDP + cb + 4];
        }
        #pragma unroll
        for (int i = 0; i < 2; i++)
            #pragma unroll
            for (int j = 0; j < 4; j++) {
                mma_bf16(acc[i][j], ah[i], bh[j]);
                mma_bf16(acc[i][j], ah[i], bl[j]);
                mma_bf16(acc[i][j], al[i], bh[j]);
            }
    }
    #pragma unroll
    for (int i = 0; i < 2; i++) {
        int m = mt * 128 + m0 + i * 16 + r;
        #pragma unroll
        for (int j = 0; j < 4; j++) {
            __half* dst = g_Sh + (h << 20) + (m << 10) + nt * 64 + n0 + j * 8 + cp2;
            *(__half2*)dst = __floats2half2_rn(acc[i][j][0] * 0.125f, acc[i][j][1] * 0.125f);
            *(__half2*)(dst + (8 << 10)) = __floats2half2_rn(acc[i][j][2] * 0.125f, acc[i][j][3] * 0.125f);
        }
    }
}

// ---------------- K6: fused geo prior + product softmax + vl + output ---------
__global__ __launch_bounds__(256) void k_attn(const float* __restrict__ wg_w,
                                              const float* __restrict__ wg_b,
                                              const float* __restrict__ logit_b,
                                              float* __restrict__ out) {
    extern __shared__ __align__(16) float sh[];
    float* G  = sh;                       // 16*1024
    ull* wgp  = (ull*)(sh + NH * NROI);   // 16*32 packed pairs
    __shared__ float wgb_s[NH];
    __shared__ float hred[NH];
    int m = blockIdx.x, t = threadIdx.x;
    for (int idx = t; idx < NH * 32; idx += 256) {
        int h = idx >> 5, j = idx & 31;
        float lo, hi;
        if (j < 16) { lo = wg_w[h*64 + 2*j];            hi = wg_w[h*64 + 2*j + 1]; }
        else { int jj = j - 16; lo = wg_w[h*64 + 32 + 2*jj]; hi = wg_w[h*64 + 32 + 2*jj + 1]; }
        wgp[idx] = pk2(lo, hi);
    }
    if (t < NH) wgb_s[t] = wg_b[t];
    float4 gm = g_geoA[m];
    float2 gi = g_geoB[m];
    __syncthreads();
    const float dmf[8] = {1.0f, 0.42169650342f, 0.17782794100f, 0.07498942093f,
                          0.03162277660f, 0.01333521432f, 0.00562341325f, 0.00237137371f};
    for (int n = t; n < NROI; n += 256) {
        float4 gn = g_geoA[n];
        float base4[4];
        base4[0] = 100.f * __logf(fmaxf(fabsf((gm.x - gn.x) * gi.x), 1e-3f));
        base4[1] = 100.f * __logf(fmaxf(fabsf((gm.y - gn.y) * gi.y), 1e-3f));
        base4[2] = 100.f * (gm.z - gn.z);
        base4[3] = 100.f * (gm.w - gn.w);
        ull ep[32];
        #pragma unroll
        for (int j2 = 0; j2 < 16; j2++) {
            int gi0 = 2 * j2, gi1 = gi0 + 1;
            float s0, c0, s1, c1;
            __sincosf(base4[gi0 >> 3] * dmf[gi0 & 7], &s0, &c0);
            __sincosf(base4[gi1 >> 3] * dmf[gi1 & 7], &s1, &c1);
            ep[j2]      = pk2(s0, s1);
            ep[16 + j2] = pk2(c0, c1);
        }
        for (int h = 0; h < NH; h++) {
            ull acc = pk2(wgb_s[h], 0.f);
            const ulonglong2* w2 = (const ulonglong2*)(wgp + h * 32);
            #pragma unroll
            for (int j2 = 0; j2 < 16; j2++) {
                ulonglong2 w = w2[j2];
                fma2(acc, ep[2 * j2],     w.x);
                fma2(acc, ep[2 * j2 + 1], w.y);
            }
            float2 f = upk(acc);
            G[(h << 10) + n] = fmaxf(f.x + f.y, 1e-6f);
        }
    }
    __syncthreads();
    int warp = t >> 5, lane = t & 31;
    for (int h = warp; h < NH; h += 8) {
        const __half2* Sh2 = (const __half2*)(g_Sh + (h << 20) + (m << 10));
        const float* vh = g_vl + (h << 10);
        const float* Gh = G + (h << 10);
        float ss = 0.f, ps = 0.f;
        for (int n2 = lane; n2 < 512; n2 += 32) {
            float2 sv = __half22float2(Sh2[n2]);
            int n = n2 * 2;
            float w0 = Gh[n]     * __expf(fminf(sv.x, 60.f));
            float w1 = Gh[n + 1] * __expf(fminf(sv.y, 60.f));
            ss += w0 + w1;
            ps += w0 * vh[n] + w1 * vh[n + 1];
        }
        #pragma unroll
        for (int o = 16; o; o >>= 1) {
            ss += __shfl_xor_sync(0xffffffffu, ss, o);
            ps += __shfl_xor_sync(0xffffffffu, ps, o);
        }
        if (lane == 0) hred[h] = ps / ss;
    }
    __syncthreads();
    if (t == 0) {
        float a = 0.f;
        for (int h = 0; h < NH; h++) a += hred[h];
        float x = a + g_sflw[m] + logit_b[0];
        float s1 = 1.0f / (1.0f + expf(-x));
        out[m] = s1 * g_sprob[m];
        out[NROI + m] = (float)(g_slabel[m] - 1);
        #pragma unroll
        for (int j = 0; j < 4; j++)
            out[2 * NROI + m * 4 + j] = g_sbbox[m * 4 + j];
    }
}

// ---------------- launch -------------------------------------------------------
extern "C" void kernel_launch(void* const* d_in, const int* in_sizes, int n_in,
                              void* d_out, int out_size) {
    const float* sample_roi  = (const float*)d_in[0];
    const float* roi_cls_loc = (const float*)d_in[1];
    const float* roi_score   = (const float*)d_in[2];
    const float* app         = (const float*)d_in[3];
    const int*   size        = (const int*)  d_in[4];
    const float* rank_w      = (const float*)d_in[5];
    const float* rank_b      = (const float*)d_in[6];
    const float* feat_w      = (const float*)d_in[7];
    const float* feat_b      = (const float*)d_in[8];
    const float* logit_w     = (const float*)d_in[9];
    const float* logit_b     = (const float*)d_in[10];
    const float* wg_w        = (const float*)d_in[11];
    const float* wg_b        = (const float*)d_in[12];
    const float* wk_w        = (const float*)d_in[13];
    const float* wk_b        = (const float*)d_in[14];
    const float* wq_w        = (const float*)d_in[15];
    const float* wq_b        = (const float*)d_in[16];
    const float* wv_w        = (const float*)d_in[17];
    const float* wv_b        = (const float*)d_in[18];
    float* out = (float*)d_out;

    const int score_smem = (2 * 128 * LDP + 2 * 64 * LDP) * (int)sizeof(u32); // 50688
    const int attn_smem  = (NH * NROI) * 4 + (NH * 32) * 8;                   // 69632
    cudaFuncSetAttribute(k_score_mma, cudaFuncAttributeMaxDynamicSharedMemorySize, score_smem);
    cudaFuncSetAttribute(k_attn, cudaFuncAttributeMaxDynamicSharedMemorySize, attn_smem);

    k_front<<<20, 256>>>(sample_roi, roi_cls_loc, roi_score, size, wv_w, wv_b, logit_w);
    k_rank<<<4, 256>>>();
    k_pre<<<256, 256>>>(app, logit_w);
    k_emb_g<<<dim3(64, 2), 256>>>(app, feat_w, rank_w, feat_b, rank_b);
    k_vl<<<128, 256>>>();
    k_kqv_g<<<dim3(8, 16), 256>>>(wk_w, wk_b, wq_w, wq_b);
    k_score_mma<<<dim3(16, 8, 16), 256, score_smem>>>();
    k_attn<<<NROI, 256, attn_smem>>>(wg_w, wg_b, logit_b, out);
}

// round 12
// speedup vs baseline: 1.9385x; 1.9385x over previous
#include <cuda_runtime.h>
#include <cuda_bf16.h>
#include <cuda_fp16.h>
#include <math.h>
#include <stdint.h>

#define NROI 1024
#define NCLS 21
#define APP  1024
#define DF   128
#define NH   16
#define DK   64

typedef unsigned long long ull;
typedef unsigned int u32;

// ---------------- f32x2 packed-math helpers (sm_103a) -------------------------
__device__ __forceinline__ ull pk2(float lo, float hi) {
    ull r; asm("mov.b64 %0,{%1,%2};" : "=l"(r) : "f"(lo), "f"(hi)); return r;
}
__device__ __forceinline__ float2 upk(ull v) {
    float2 f; asm("mov.b64 {%0,%1},%2;" : "=f"(f.x), "=f"(f.y) : "l"(v)); return f;
}
__device__ __forceinline__ void fma2(ull &c, ull a, ull b) {
    asm("fma.rn.f32x2 %0,%1,%2,%0;" : "+l"(c) : "l"(a), "l"(b));
}

// ---------------- HMMA m16n8k16 bf16 ------------------------------------------
__device__ __forceinline__ void mma_bf16(float* c, const u32* a, const u32* b) {
    asm volatile("mma.sync.aligned.m16n8k16.row.col.f32.bf16.bf16.f32 "
        "{%0,%1,%2,%3},{%4,%5,%6,%7},{%8,%9},{%0,%1,%2,%3};"
        : "+f"(c[0]), "+f"(c[1]), "+f"(c[2]), "+f"(c[3])
        : "r"(a[0]), "r"(a[1]), "r"(a[2]), "r"(a[3]), "r"(b[0]), "r"(b[1]));
}

// ---------------- scratch (device globals; no allocation allowed) -------------
__device__ __half g_Sh[NH * NROI * NROI];     // 32 MB scores fp16 [h][m][n]
__device__ __align__(16) __nv_bfloat16 g_Kh[NH*NROI*DK], g_Kl[NH*NROI*DK];
__device__ __align__(16) __nv_bfloat16 g_Qh[NH*NROI*DK], g_Ql[NH*NROI*DK];
__device__ __align__(16) float g_emb[NROI * DF];
__device__ float g_vl[NH * NROI];
__device__ float g_wvl[NH * DF];
__device__ float g_bvl[NH];
__device__ float g_prob[NROI], g_sprob[NROI], g_sflw[NROI];
__device__ float g_bbox[NROI * 4], g_sbbox[NROI * 4];
__device__ __align__(16) float4 g_geoA[NROI];   // cx, cy, log w, log h
__device__ __align__(8)  float2 g_geoB[NROI];   // 1/w, 1/h
__device__ int   g_label[NROI], g_slabel[NROI], g_order[NROI];

// ---------------- K1: per-ROI decode (blocks 0-3) + wvl (blocks 4-19) ---------
__global__ __launch_bounds__(256) void k_front(const float* __restrict__ roi,
                                               const float* __restrict__ cls_loc,
                                               const float* __restrict__ score,
                                               const int*   __restrict__ size,
                                               const float* __restrict__ wv_w,
                                               const float* __restrict__ wv_b,
                                               const float* __restrict__ lw) {
    __shared__ float lwh[DK];
    int b = blockIdx.x, t = threadIdx.x;
    if (b < 4) {
        int i = b * 256 + t;
        const float* s = score + i * NCLS;
        float mx = -1e30f; int am = 0;
        for (int c = 0; c < NCLS; c++) { float v = s[c]; if (v > mx) { mx = v; am = c; } }
        float sum = 0.f;
        for (int c = 0; c < NCLS; c++) sum += expf(s[c] - mx);
        g_prob[i] = 1.0f / sum;
        g_label[i] = am;
        float y0 = roi[i*4+0], x0 = roi[i*4+1], y1 = roi[i*4+2], x1 = roi[i*4+3];
        float h = y1 - y0, w = x1 - x0;
        float cy = y0 + 0.5f * h, cx = x0 + 0.5f * w;
        const float* l = cls_loc + i * (NCLS*4) + am * 4;
        float dy = l[0]*0.1f, dx = l[1]*0.1f, dh = l[2]*0.2f, dw = l[3]*0.2f;
        float ncy = dy*h + cy, ncx = dx*w + cx;
        float nh = expf(dh)*h, nw = expf(dw)*w;
        float b0 = ncy - 0.5f*nh, b1 = ncx - 0.5f*nw, b2 = ncy + 0.5f*nh, b3 = ncx + 0.5f*nw;
        // reference clamp quirk: even class -> all coords clamp to size[0], odd -> size[1]
        float lim = ((am & 1) == 0) ? (float)size[0] : (float)size[1];
        b0 = fminf(fmaxf(b0, 0.f), lim); b1 = fminf(fmaxf(b1, 0.f), lim);
        b2 = fminf(fmaxf(b2, 0.f), lim); b3 = fminf(fmaxf(b3, 0.f), lim);
        g_bbox[i*4+0]=b0; g_bbox[i*4+1]=b1; g_bbox[i*4+2]=b2; g_bbox[i*4+3]=b3;
        return;
    }
    int h = b - 4;
    if (t < DK) lwh[t] = lw[h * DK + t];
    __syncthreads();
    int d = t >> 1, half = t & 1;
    const float4* W  = (const float4*)(wv_w + (h * DF + d) * DK + half * 32);
    float a = 0.f;
    #pragma unroll
    for (int q = 0; q < 8; q++) {
        float4 w4 = W[q];
        const float* l4 = lwh + half * 32 + q * 4;
        a += w4.x*l4[0] + w4.y*l4[1] + w4.z*l4[2] + w4.w*l4[3];
    }
    a += __shfl_xor_sync(0xffffffffu, a, 1);
    if (!half) g_wvl[h * DF + d] = a;
    if (t < 32) {
        float pb = wv_b[h*DK + t] * lwh[t] + wv_b[h*DK + t + 32] * lwh[t + 32];
        #pragma unroll
        for (int o = 16; o; o >>= 1) pb += __shfl_xor_sync(0xffffffffu, pb, o);
        if (t == 0) g_bvl[h] = pb;
    }
}

// ---------------- K2: stable descending rank + scatter ------------------------
__global__ __launch_bounds__(256) void k_rank() {
    __shared__ float sp[NROI];
    int t = threadIdx.x;
    int i = blockIdx.x * 256 + t;
    for (int j = t; j < NROI; j += 256) sp[j] = g_prob[j];
    __syncthreads();
    float p = sp[i];
    int r = 0;
    for (int j = 0; j < NROI; j++) {
        float pj = sp[j];
        r += (pj > p) || (pj == p && j < i);
    }
    g_order[r]  = i;
    g_sprob[r]  = p;
    g_slabel[r] = g_label[i];
    float b0=g_bbox[i*4+0], b1=g_bbox[i*4+1], b2=g_bbox[i*4+2], b3=g_bbox[i*4+3];
    g_sbbox[r*4+0]=b0; g_sbbox[r*4+1]=b1; g_sbbox[r*4+2]=b2; g_sbbox[r*4+3]=b3;
    float cx = (b0+b2)*0.5f, cy = (b1+b3)*0.5f;
    float w  = (b2-b0)+1.0f, h  = (b3-b1)+1.0f;
    g_geoA[r] = make_float4(cx, cy, logf(w), logf(h));
    g_geoB[r] = make_float2(1.0f / w, 1.0f / h);
}

// ---------------- K3: emb = sf@feat_w + RE@rank_w + biases  (BM=8, 256 thr) ---
// reduction dim (1024) split across 2 thread-halves; partials merged via smem
__global__ __launch_bounds__(256) void k_emb(const float* __restrict__ app,
                                             const float* __restrict__ rank_w,
                                             const float* __restrict__ rank_b,
                                             const float* __restrict__ feat_w,
                                             const float* __restrict__ feat_b,
                                             const float* __restrict__ lw) {
    __shared__ __align__(16) float arow[8][APP];
    __shared__ __align__(16) float rerow[8][APP];
    __shared__ int   s_oi[8];
    __shared__ float s_pl[8];
    __shared__ float s_part[8][DF];
    int i0 = blockIdx.x * 8, t = threadIdx.x;
    if (t < 8) s_oi[t] = g_order[i0 + t];
    __syncthreads();
    // coalesced row loads (warp per row) + sflw dot
    int row = t >> 5, lane = t & 31;
    {
        const float4* src = (const float4*)(app + s_oi[row] * APP);
        const float4* lw4 = (const float4*)lw;
        float pl = 0.f;
        #pragma unroll
        for (int q = 0; q < 8; q++) {
            int j4 = lane + q * 32;
            float4 a = src[j4];
            *(float4*)&arow[row][j4 * 4] = a;
            float4 l = lw4[j4];
            pl += a.x*l.x + a.y*l.y + a.z*l.z + a.w*l.w;
        }
        #pragma unroll
        for (int o = 16; o; o >>= 1) pl += __shfl_xor_sync(0xffffffffu, pl, o);
        if (lane == 0) s_pl[row] = pl;
    }
    // rank embedding: recurrence across the 8 rows; 2 freqs per thread
    const float LOGW = 6.90775527898f / 512.0f;
    #pragma unroll
    for (int fi = 0; fi < 2; fi++) {
        int f = t + fi * 256;
        float a = expf(-(float)f * LOGW);
        float s0, c0, sa, ca;
        sincosf((float)i0 * a, &s0, &c0);
        sincosf(a, &sa, &ca);
        #pragma unroll
        for (int r = 0; r < 8; r++) {
            rerow[r][f] = s0; rerow[r][f + 512] = c0;
            float s1 = s0*ca + c0*sa, c1 = c0*ca - s0*sa;
            s0 = s1; c0 = c1;
        }
    }
    __syncthreads();
    int col = t & 127, kh = t >> 7;       // two k-halves
    ull acc[8];
    #pragma unroll
    for (int r = 0; r < 8; r++) acc[r] = 0ull;
    int jbase = kh * 512;
    for (int j4 = 0; j4 < 128; j4++) {
        int jb = jbase + j4 * 4;
        ull fp01 = pk2(feat_w[(jb+0)*DF + col], feat_w[(jb+1)*DF + col]);
        ull fp23 = pk2(feat_w[(jb+2)*DF + col], feat_w[(jb+3)*DF + col]);
        ull rp01 = pk2(rank_w[(jb+0)*DF + col], rank_w[(jb+1)*DF + col]);
        ull rp23 = pk2(rank_w[(jb+2)*DF + col], rank_w[(jb+3)*DF + col]);
        #pragma unroll
        for (int r = 0; r < 8; r++) {
            ulonglong2 a2 = *(const ulonglong2*)&arow[r][jb];
            ulonglong2 e2 = *(const ulonglong2*)&rerow[r][jb];
            fma2(acc[r], a2.x, fp01); fma2(acc[r], a2.y, fp23);
            fma2(acc[r], e2.x, rp01); fma2(acc[r], e2.y, rp23);
        }
    }
    if (kh == 0) {
        #pragma unroll
        for (int r = 0; r < 8; r++) {
            float2 v = upk(acc[r]);
            s_part[r][col] = v.x + v.y;
        }
    }
    __syncthreads();
    if (kh == 1) {
        float bias = feat_b[col] + rank_b[col];
        #pragma unroll
        for (int r = 0; r < 8; r++) {
            float2 v = upk(acc[r]);
            g_emb[(i0 + r) * DF + col] = v.x + v.y + s_part[r][col] + bias;
        }
    }
    if (t < 8) g_sflw[i0 + t] = s_pl[t];
}

// ---------------- K4: k/q projections (512 thr, 4 cols each) + vl -------------
__global__ __launch_bounds__(512) void k_kqv(const float* __restrict__ wk_w,
                                             const float* __restrict__ wk_b,
                                             const float* __restrict__ wq_w,
                                             const float* __restrict__ wq_b) {
    __shared__ __align__(16) float es[DF][8];
    int i0 = blockIdx.x * 8, t = threadIdx.x;
    for (int idx = t; idx < 8 * DF; idx += 512) {
        int r = idx >> 7, d = idx & 127;
        es[d][r] = g_emb[(i0 + r) * DF + d];
    }
    __syncthreads();
    const float* wp[4]; float bias[4];
    #pragma unroll
    for (int c = 0; c < 4; c++) {
        int p = t + (c << 9);
        if (p < 1024) { int h = p >> 6, kk = p & 63; wp[c] = wk_w + h * DF * DK + kk; bias[c] = wk_b[p]; }
        else          { int q = p - 1024; int h = q >> 6, kk = q & 63; wp[c] = wq_w + h * DF * DK + kk; bias[c] = wq_b[q]; }
    }
    ull acc[4][4];
    #pragma unroll
    for (int c = 0; c < 4; c++)
        #pragma unroll
        for (int rp = 0; rp < 4; rp++) acc[c][rp] = 0ull;
    for (int d = 0; d < DF; d++) {
        ulonglong2 e0123 = *(const ulonglong2*)&es[d][0];
        ulonglong2 e4567 = *(const ulonglong2*)&es[d][4];
        #pragma unroll
        for (int c = 0; c < 4; c++) {
            float w = wp[c][d << 6];
            ull wd = pk2(w, w);
            fma2(acc[c][0], e0123.x, wd);
            fma2(acc[c][1], e0123.y, wd);
            fma2(acc[c][2], e4567.x, wd);
            fma2(acc[c][3], e4567.y, wd);
        }
    }
    #pragma unroll
    for (int c = 0; c < 4; c++) {
        int p = t + (c << 9);
        bool isK = (p < 1024);
        int pp = isK ? p : p - 1024;
        int h = pp >> 6, kk = pp & 63;
        #pragma unroll
        for (int rp = 0; rp < 4; rp++) {
            float2 v = upk(acc[c][rp]);
            #pragma unroll
            for (int e = 0; e < 2; e++) {
                float val = ((e == 0) ? v.x : v.y) + bias[c];
                int idx = (h * NROI + i0 + 2*rp + e) * DK + kk;
                __nv_bfloat16 hi = __float2bfloat16(val);
                __nv_bfloat16 lo = __float2bfloat16(val - __bfloat162float(hi));
                if (isK) { g_Kh[idx] = hi; g_Kl[idx] = lo; }
                else     { g_Qh[idx] = hi; g_Ql[idx] = lo; }
            }
        }
    }
    if (t < 128) {
        int h = t >> 3, r = t & 7;
        float a = g_bvl[h];
        for (int d = 0; d < DF; d++) a += es[d][r] * g_wvl[h * DF + d];
        g_vl[(h << 10) + i0 + r] = a;
    }
}

// ---------------- K5: HMMA bf16-split score GEMM -> fp16 S --------------------
#define LDP 33
__global__ __launch_bounds__(256) void k_score_mma() {
    extern __shared__ __align__(16) u32 sm[];
    u32* KHs = sm;
    u32* KLs = sm + 128 * LDP;
    u32* QHs = sm + 2 * 128 * LDP;
    u32* QLs = sm + 2 * 128 * LDP + 64 * LDP;
    int t = threadIdx.x;
    int nt = blockIdx.x, mt = blockIdx.y, h = blockIdx.z;
    const u32* gKH = (const u32*)g_Kh + ((h << 10) + mt * 128) * 32;
    const u32* gKL = (const u32*)g_Kl + ((h << 10) + mt * 128) * 32;
    const u32* gQH = (const u32*)g_Qh + ((h << 10) + nt * 64) * 32;
    const u32* gQL = (const u32*)g_Ql + ((h << 10) + nt * 64) * 32;
    #pragma unroll
    for (int it = 0; it < 16; it++) {
        int idx = t + it * 256;
        int row = idx >> 5, c = idx & 31;
        KHs[row * LDP + c] = gKH[idx];
        KLs[row * LDP + c] = gKL[idx];
    }
    #pragma unroll
    for (int it = 0; it < 8; it++) {
        int idx = t + it * 256;
        int row = idx >> 5, c = idx & 31;
        QHs[row * LDP + c] = gQH[idx];
        QLs[row * LDP + c] = gQL[idx];
    }
    __syncthreads();
    int wid = t >> 5, lane = t & 31;
    int m0 = (wid >> 1) * 32, n0 = (wid & 1) * 32;
    int r = lane >> 2, cp2 = (lane & 3) * 2;
    float acc[2][4][4];
    #pragma unroll
    for (int i = 0; i < 2; i++)
        #pragma unroll
        for (int j = 0; j < 4; j++)
            #pragma unroll
            for (int e = 0; e < 4; e++) acc[i][j][e] = 0.f;
    #pragma unroll
    for (int kc = 0; kc < 4; kc++) {
        int cb = kc * 8 + (cp2 >> 1);
        u32 ah[2][4], al[2][4];
        #pragma unroll
        for (int i = 0; i < 2; i++) {
            int ra = m0 + i * 16 + r;
            ah[i][0] = KHs[ra * LDP + cb];       al[i][0] = KLs[ra * LDP + cb];
            ah[i][1] = KHs[(ra+8) * LDP + cb];   al[i][1] = KLs[(ra+8) * LDP + cb];
            ah[i][2] = KHs[ra * LDP + cb + 4];   al[i][2] = KLs[ra * LDP + cb + 4];
            ah[i][3] = KHs[(ra+8) * LDP + cb+4]; al[i][3] = KLs[(ra+8) * LDP + cb+4];
        }
        u32 bh[4][2], bl[4][2];
        #pragma unroll
        for (int j = 0; j < 4; j++) {
            int rb = n0 + j * 8 + r;
            bh[j][0] = QHs[rb * LDP + cb];     bl[j][0] = QLs[rb * LDP + cb];
            bh[j][1] = QHs[rb * LDP + cb + 4]; bl[j][1] = QLs[rb * LDP + cb + 4];
        }
        #pragma unroll
        for (int i = 0; i < 2; i++)
            #pragma unroll
            for (int j = 0; j < 4; j++) {
                mma_bf16(acc[i][j], ah[i], bh[j]);
                mma_bf16(acc[i][j], ah[i], bl[j]);
                mma_bf16(acc[i][j], al[i], bh[j]);
            }
    }
    #pragma unroll
    for (int i = 0; i < 2; i++) {
        int m = mt * 128 + m0 + i * 16 + r;
        #pragma unroll
        for (int j = 0; j < 4; j++) {
            __half* dst = g_Sh + (h << 20) + (m << 10) + nt * 64 + n0 + j * 8 + cp2;
            *(__half2*)dst = __floats2half2_rn(acc[i][j][0] * 0.125f, acc[i][j][1] * 0.125f);
            *(__half2*)(dst + (8 << 10)) = __floats2half2_rn(acc[i][j][2] * 0.125f, acc[i][j][3] * 0.125f);
        }
    }
}

// ---------------- K6: fused geo prior + product softmax + vl + output ---------
__global__ __launch_bounds__(256) void k_attn(const float* __restrict__ wg_w,
                                              const float* __restrict__ wg_b,
                                              const float* __restrict__ logit_b,
                                              float* __restrict__ out) {
    extern __shared__ __align__(16) float sh[];
    float* G  = sh;                       // 16*1024
    ull* wgp  = (ull*)(sh + NH * NROI);   // 16*32 packed pairs
    __shared__ float wgb_s[NH];
    __shared__ float hred[NH];
    int m = blockIdx.x, t = threadIdx.x;
    for (int idx = t; idx < NH * 32; idx += 256) {
        int h = idx >> 5, j = idx & 31;
        float lo, hi;
        if (j < 16) { lo = wg_w[h*64 + 2*j];            hi = wg_w[h*64 + 2*j + 1]; }
        else { int jj = j - 16; lo = wg_w[h*64 + 32 + 2*jj]; hi = wg_w[h*64 + 32 + 2*jj + 1]; }
        wgp[idx] = pk2(lo, hi);
    }
    if (t < NH) wgb_s[t] = wg_b[t];
    float4 gm = g_geoA[m];
    float2 gi = g_geoB[m];
    __syncthreads();
    const float dmf[8] = {1.0f, 0.42169650342f, 0.17782794100f, 0.07498942093f,
                          0.03162277660f, 0.01333521432f, 0.00562341325f, 0.00237137371f};
    for (int n = t; n < NROI; n += 256) {
        float4 gn = g_geoA[n];
        float base4[4];
        base4[0] = 100.f * __logf(fmaxf(fabsf((gm.x - gn.x) * gi.x), 1e-3f));
        base4[1] = 100.f * __logf(fmaxf(fabsf((gm.y - gn.y) * gi.y), 1e-3f));
        base4[2] = 100.f * (gm.z - gn.z);
        base4[3] = 100.f * (gm.w - gn.w);
        ull ep[32];
        #pragma unroll
        for (int j2 = 0; j2 < 16; j2++) {
            int gi0 = 2 * j2, gi1 = gi0 + 1;
            float s0, c0, s1, c1;
            __sincosf(base4[gi0 >> 3] * dmf[gi0 & 7], &s0, &c0);
            __sincosf(base4[gi1 >> 3] * dmf[gi1 & 7], &s1, &c1);
            ep[j2]      = pk2(s0, s1);
            ep[16 + j2] = pk2(c0, c1);
        }
        for (int h = 0; h < NH; h++) {
            ull acc = pk2(wgb_s[h], 0.f);
            const ulonglong2* w2 = (const ulonglong2*)(wgp + h * 32);
            #pragma unroll
            for (int j2 = 0; j2 < 16; j2++) {
                ulonglong2 w = w2[j2];
                fma2(acc, ep[2 * j2],     w.x);
                fma2(acc, ep[2 * j2 + 1], w.y);
            }
            float2 f = upk(acc);
            G[(h << 10) + n] = fmaxf(f.x + f.y, 1e-6f);
        }
    }
    __syncthreads();
    int warp = t >> 5, lane = t & 31;
    for (int h = warp; h < NH; h += 8) {
        const __half2* Sh2 = (const __half2*)(g_Sh + (h << 20) + (m << 10));
        const float* vh = g_vl + (h << 10);
        const float* Gh = G + (h << 10);
        float ss = 0.f, ps = 0.f;
        for (int n2 = lane; n2 < 512; n2 += 32) {
            float2 sv = __half22float2(Sh2[n2]);
            int n = n2 * 2;
            float w0 = Gh[n]     * __expf(fminf(sv.x, 60.f));
            float w1 = Gh[n + 1] * __expf(fminf(sv.y, 60.f));
            ss += w0 + w1;
            ps += w0 * vh[n] + w1 * vh[n + 1];
        }
        #pragma unroll
        for (int o = 16; o; o >>= 1) {
            ss += __shfl_xor_sync(0xffffffffu, ss, o);
            ps += __shfl_xor_sync(0xffffffffu, ps, o);
        }
        if (lane == 0) hred[h] = ps / ss;
    }
    __syncthreads();
    if (t == 0) {
        float a = 0.f;
        for (int h = 0; h < NH; h++) a += hred[h];
        float x = a + g_sflw[m] + logit_b[0];
        float s1 = 1.0f / (1.0f + expf(-x));
        out[m] = s1 * g_sprob[m];
        out[NROI + m] = (float)(g_slabel[m] - 1);
        #pragma unroll
        for (int j = 0; j < 4; j++)
            out[2 * NROI + m * 4 + j] = g_sbbox[m * 4 + j];
    }
}

// ---------------- launch -------------------------------------------------------
extern "C" void kernel_launch(void* const* d_in, const int* in_sizes, int n_in,
                              void* d_out, int out_size) {
    const float* sample_roi  = (const float*)d_in[0];
    const float* roi_cls_loc = (const float*)d_in[1];
    const float* roi_score   = (const float*)d_in[2];
    const float* app         = (const float*)d_in[3];
    const int*   size        = (const int*)  d_in[4];
    const float* rank_w      = (const float*)d_in[5];
    const float* rank_b      = (const float*)d_in[6];
    const float* feat_w      = (const float*)d_in[7];
    const float* feat_b      = (const float*)d_in[8];
    const float* logit_w     = (const float*)d_in[9];
    const float* logit_b     = (const float*)d_in[10];
    const float* wg_w        = (const float*)d_in[11];
    const float* wg_b        = (const float*)d_in[12];
    const float* wk_w        = (const float*)d_in[13];
    const float* wk_b        = (const float*)d_in[14];
    const float* wq_w        = (const float*)d_in[15];
    const float* wq_b        = (const float*)d_in[16];
    const float* wv_w        = (const float*)d_in[17];
    const float* wv_b        = (const float*)d_in[18];
    float* out = (float*)d_out;

    const int score_smem = (2 * 128 * LDP + 2 * 64 * LDP) * (int)sizeof(u32); // 50688
    const int attn_smem  = (NH * NROI) * 4 + (NH * 32) * 8;                   // 69632
    cudaFuncSetAttribute(k_score_mma, cudaFuncAttributeMaxDynamicSharedMemorySize, score_smem);
    cudaFuncSetAttribute(k_attn, cudaFuncAttributeMaxDynamicSharedMemorySize, attn_smem);

    k_front<<<20, 256>>>(sample_roi, roi_cls_loc, roi_score, size, wv_w, wv_b, logit_w);
    k_rank<<<4, 256>>>();
    k_emb<<<NROI / 8, 256>>>(app, rank_w, rank_b, feat_w, feat_b, logit_w);
    k_kqv<<<NROI / 8, 512>>>(wk_w, wk_b, wq_w, wq_b);
    k_score_mma<<<dim3(16, 8, 16), 256, score_smem>>>();
    k_attn<<<NROI, 256, attn_smem>>>(wg_w, wg_b, logit_b, out);
}